// round 14
// baseline (speedup 1.0000x reference)
#include <cuda_runtime.h>
#include <cuda_bf16.h>

// ---------------------------------------------------------------------------
// MultiHeadAttention round 13 — bf16 end-to-end:
//   one merged W->bf16 convert, LN->bf16, fused QKV proj (bf16 MMA, cp.async),
//   vpair, flash attention (bf16, P in registers, DOUBLE-BUFFERED K/V smem,
//   2 barriers/iter), out proj fp32 epilogue + residual.
// ---------------------------------------------------------------------------

#define HIDDEN 1024
#define SEQ    2048
#define BATCH  2
#define HEADS  16
#define HEADD  64
#define ROWS   (BATCH * SEQ)          // 4096
#define HHALF  (HIDDEN / 2)           // 512 u32 per row of bf16

__device__ unsigned short g_xn [ROWS * HIDDEN];   // bf16
__device__ unsigned short g_q  [ROWS * HIDDEN];   // bf16
__device__ unsigned short g_k  [ROWS * HIDDEN];   // bf16
__device__ unsigned short g_v  [ROWS * HIDDEN];   // bf16
__device__ unsigned short g_ctx[ROWS * HIDDEN];   // bf16
__device__ unsigned       g_vp [BATCH * (SEQ/2) * HIDDEN]; // paired V, u32
__device__ unsigned short g_w  [4][HIDDEN * HIDDEN];       // bf16 Wq,Wk,Wv,Wo

// ---------------------------------------------------------------------------
__device__ __forceinline__ unsigned pack_bf16(float lo, float hi) {
    unsigned r;
    asm("cvt.rn.bf16x2.f32 %0, %1, %2;" : "=r"(r) : "f"(hi), "f"(lo));
    return r;   // lo -> lower half, hi -> upper half
}

__device__ __forceinline__ void mma16(float* c,
    unsigned a0, unsigned a1, unsigned a2, unsigned a3,
    unsigned b0, unsigned b1)
{
    asm volatile(
        "mma.sync.aligned.m16n8k16.row.col.f32.bf16.bf16.f32 "
        "{%0,%1,%2,%3},{%4,%5,%6,%7},{%8,%9},{%0,%1,%2,%3};"
        : "+f"(c[0]), "+f"(c[1]), "+f"(c[2]), "+f"(c[3])
        : "r"(a0), "r"(a1), "r"(a2), "r"(a3), "r"(b0), "r"(b1));
}

__device__ __forceinline__ void cp16(void* sp, const void* gp) {
    unsigned sa = (unsigned)__cvta_generic_to_shared(sp);
    asm volatile("cp.async.cg.shared.global [%0], [%1], 16;" :: "r"(sa), "l"(gp));
}
#define CP_COMMIT() asm volatile("cp.async.commit_group;")
#define CP_WAIT1()  asm volatile("cp.async.wait_group 1;")
#define CP_WAIT0()  asm volatile("cp.async.wait_group 0;")

__device__ __forceinline__ float blockReduceSum(float v, float* sh) {
    int lane = threadIdx.x & 31, w = threadIdx.x >> 5;
    #pragma unroll
    for (int o = 16; o; o >>= 1) v += __shfl_down_sync(0xFFFFFFFFu, v, o);
    if (lane == 0) sh[w] = v;
    __syncthreads();
    float r = 0.0f;
    if (w == 0) {
        r = (lane < (int)(blockDim.x >> 5)) ? sh[lane] : 0.0f;
        #pragma unroll
        for (int o = 16; o; o >>= 1) r += __shfl_down_sync(0xFFFFFFFFu, r, o);
        if (lane == 0) sh[0] = r;
    }
    __syncthreads();
    r = sh[0];
    __syncthreads();
    return r;
}

// ---------------------------------------------------------------------------
// Merged weight fp32 -> bf16 convert: blockIdx.y selects matrix (4x 1M elems).
// ---------------------------------------------------------------------------
__global__ __launch_bounds__(256) void convw_kernel(
    const float* __restrict__ w0, const float* __restrict__ w1,
    const float* __restrict__ w2, const float* __restrict__ w3,
    unsigned* __restrict__ dst2)
{
    const float* src = (blockIdx.y == 0) ? w0 : (blockIdx.y == 1) ? w1
                     : (blockIdx.y == 2) ? w2 : w3;
    unsigned* dst = dst2 + (long long)blockIdx.y * (HIDDEN * HHALF);
    int id = blockIdx.x * 256 + threadIdx.x;          // 0 .. 262143
    float4 v = ((const float4*)src)[id];
    ((uint2*)dst)[id] = make_uint2(pack_bf16(v.x, v.y), pack_bf16(v.z, v.w));
}

// ---------------------------------------------------------------------------
// LayerNorm: one block (256 threads) per row; outputs bf16.
// ---------------------------------------------------------------------------
__global__ __launch_bounds__(256) void ln_kernel(
    const float* __restrict__ x, const float* __restrict__ g,
    const float* __restrict__ b, unsigned* __restrict__ xn2)
{
    __shared__ float sh[32];
    long long row = blockIdx.x;
    const float4 v = ((const float4*)(x + row * HIDDEN))[threadIdx.x];
    float s  = v.x + v.y + v.z + v.w;
    float sq = v.x*v.x + v.y*v.y + v.z*v.z + v.w*v.w;
    s  = blockReduceSum(s,  sh);
    sq = blockReduceSum(sq, sh);
    float mu  = s  * (1.0f / HIDDEN);
    float var = sq * (1.0f / HIDDEN) - mu * mu;
    float inv = rsqrtf(var + 1e-5f);
    float4 gg = ((const float4*)g)[threadIdx.x];
    float4 bb = ((const float4*)b)[threadIdx.x];
    float ox = (v.x - mu) * inv * gg.x + bb.x;
    float oy = (v.y - mu) * inv * gg.y + bb.y;
    float oz = (v.z - mu) * inv * gg.z + bb.z;
    float ow = (v.w - mu) * inv * gg.w + bb.w;
    ((uint2*)(xn2 + row * HHALF))[threadIdx.x] =
        make_uint2(pack_bf16(ox, oy), pack_bf16(oz, ow));
}

// ---------------------------------------------------------------------------
// V pair kernel: vp[b*1024 + j][c] = {lo = v[b*2048+2j][c], hi = v[...2j+1][c]}
// ---------------------------------------------------------------------------
__global__ __launch_bounds__(256) void vpair_kernel(
    const unsigned short* __restrict__ vbf, unsigned* __restrict__ vp)
{
    int id = blockIdx.x * 256 + threadIdx.x;          // 0 .. 524287
    int b  = id >> 18;
    int jb = id & 262143;
    int j  = jb >> 8;
    int c0 = (jb & 255) * 4;
    const unsigned* ra = (const unsigned*)(vbf + ((long long)(b*SEQ + 2*j)     * HIDDEN) + c0);
    const unsigned* rb = (const unsigned*)(vbf + ((long long)(b*SEQ + 2*j + 1) * HIDDEN) + c0);
    uint2 a = *(const uint2*)ra;
    uint2 bq = *(const uint2*)rb;
    uint4 o;
    o.x = (a.x & 0xFFFFu) | (bq.x << 16);
    o.y = (a.x >> 16)     | (bq.x & 0xFFFF0000u);
    o.z = (a.y & 0xFFFFu) | (bq.y << 16);
    o.w = (a.y >> 16)     | (bq.y & 0xFFFF0000u);
    *(uint4*)(vp + ((long long)(b*1024 + j)) * HIDDEN + c0) = o;
}

// ---------------------------------------------------------------------------
// bf16 GEMM, 128x128x64 tile, 2-stage cp.async, 2 CTAs/SM.
// ---------------------------------------------------------------------------
#define TBM 128
#define TBN 128
#define TBKH 64                        // K halves per tile
#define GSTR 36                        // u32 stride (32 data + 4 pad)
#define G_STG (TBM * GSTR)             // 4608 u32
#define GEMM_SMEM ((4 * G_STG) * 4)    // 73728 B

struct GemmPtrs {
    const unsigned short* W[3];
    const float*          bias[3];
    void*                 C[3];
};

template<bool OUT_FP32>
__global__ __launch_bounds__(256, 2) void gemm_bf16_db_kernel(
    const unsigned short* __restrict__ A, GemmPtrs p,
    const float* __restrict__ resid)
{
    extern __shared__ unsigned gsm[];
    unsigned (*As)[TBM][GSTR] = (unsigned(*)[TBM][GSTR])gsm;
    unsigned (*Bs)[TBM][GSTR] = (unsigned(*)[TBM][GSTR])(gsm + 2 * G_STG);

    const int z = blockIdx.z;
    const unsigned short* __restrict__ B = p.W[z];
    const float* __restrict__ bias = p.bias[z];

    const int tid  = threadIdx.x;
    const int lane = tid & 31;
    const int wid  = tid >> 5;
    const int wm   = wid & 3;
    const int wn   = wid >> 2;
    const int qr   = lane >> 2;
    const int qc   = lane & 3;
    const int i0   = blockIdx.y * TBM;
    const int j0   = blockIdx.x * TBN;

    const int l_r = tid >> 3;
    const int l_h = (tid & 7) * 8;
    const int l_u = (tid & 7) * 4;

    const int NT = HIDDEN / TBKH;      // 16

    #pragma unroll
    for (int it = 0; it < 4; ++it)
        cp16(&As[0][l_r + it * 32][l_u],
             A + (long long)(i0 + l_r + it * 32) * HIDDEN + l_h);
    #pragma unroll
    for (int it = 0; it < 4; ++it)
        cp16(&Bs[0][l_r + it * 32][l_u],
             B + (long long)(j0 + l_r + it * 32) * HIDDEN + l_h);
    CP_COMMIT();

    float acc[2][8][4];
    #pragma unroll
    for (int mi = 0; mi < 2; ++mi)
        #pragma unroll
        for (int ni = 0; ni < 8; ++ni)
            #pragma unroll
            for (int r = 0; r < 4; ++r) acc[mi][ni][r] = 0.0f;

    for (int t = 0; t < NT; ++t) {
        if (t + 1 < NT) {
            const int k0 = (t + 1) * TBKH;
            const int s  = (t + 1) & 1;
            #pragma unroll
            for (int it = 0; it < 4; ++it)
                cp16(&As[s][l_r + it * 32][l_u],
                     A + (long long)(i0 + l_r + it * 32) * HIDDEN + (k0 + l_h));
            #pragma unroll
            for (int it = 0; it < 4; ++it)
                cp16(&Bs[s][l_r + it * 32][l_u],
                     B + (long long)(j0 + l_r + it * 32) * HIDDEN + (k0 + l_h));
        }
        CP_COMMIT();
        CP_WAIT1();
        __syncthreads();

        const int s = t & 1;
        #pragma unroll
        for (int ks = 0; ks < 4; ++ks) {
            const int kb = ks * 8;
            unsigned a[2][4], b[8][2];
            #pragma unroll
            for (int mi = 0; mi < 2; ++mi) {
                int r = wm * 32 + mi * 16 + qr;
                a[mi][0] = As[s][r][kb + qc];
                a[mi][1] = As[s][r + 8][kb + qc];
                a[mi][2] = As[s][r][kb + qc + 4];
                a[mi][3] = As[s][r + 8][kb + qc + 4];
            }
            #pragma unroll
            for (int ni = 0; ni < 8; ++ni) {
                int c = wn * 64 + ni * 8 + qr;
                b[ni][0] = Bs[s][c][kb + qc];
                b[ni][1] = Bs[s][c][kb + qc + 4];
            }
            #pragma unroll
            for (int mi = 0; mi < 2; ++mi)
                #pragma unroll
                for (int ni = 0; ni < 8; ++ni)
                    mma16(acc[mi][ni], a[mi][0], a[mi][1], a[mi][2], a[mi][3],
                          b[ni][0], b[ni][1]);
        }
        __syncthreads();
    }

    #pragma unroll
    for (int mi = 0; mi < 2; ++mi) {
        const int r0 = i0 + wm * 32 + mi * 16 + qr;
        #pragma unroll
        for (int ni = 0; ni < 8; ++ni) {
            const int c = j0 + wn * 64 + ni * 8 + qc * 2;
            float bx = bias[c], by = bias[c + 1];
            if (OUT_FP32) {
                float* C = (float*)p.C[z];
                {
                    long long off = (long long)r0 * HIDDEN + c;
                    float2 v;
                    v.x = acc[mi][ni][0] + bx;
                    v.y = acc[mi][ni][1] + by;
                    if (resid) { float2 rr = *(const float2*)&resid[off];
                                 v.x += rr.x; v.y += rr.y; }
                    *(float2*)&C[off] = v;
                }
                {
                    long long off = (long long)(r0 + 8) * HIDDEN + c;
                    float2 v;
                    v.x = acc[mi][ni][2] + bx;
                    v.y = acc[mi][ni][3] + by;
                    if (resid) { float2 rr = *(const float2*)&resid[off];
                                 v.x += rr.x; v.y += rr.y; }
                    *(float2*)&C[off] = v;
                }
            } else {
                unsigned* C = (unsigned*)p.C[z];
                const int cu = c >> 1;
                C[(long long)r0 * HHALF + cu] =
                    pack_bf16(acc[mi][ni][0] + bx, acc[mi][ni][1] + by);
                C[(long long)(r0 + 8) * HHALF + cu] =
                    pack_bf16(acc[mi][ni][2] + bx, acc[mi][ni][3] + by);
            }
        }
    }
}

// ---------------------------------------------------------------------------
// Flash attention, bf16 m16n8k16, DOUBLE-BUFFERED K/V, 2 barriers/iter.
// Smem (u32): Qs[128][36] + Ks[2][128][36] + Vp[2][64][68] = 90112 B.
// Group ledger: G0={Q,K0,V0}, G1={K1,V1}, G(t+2) committed end of iter t.
//   top-of-iter: wait_group 1 (t+1<NT) else wait_group 0  -> G(t) resident.
// Per iter: wait, sync, QK(buf t&1) + softmax + PV(buf t&1), sync,
//           commit G(t+2) into buf t&1.
// ---------------------------------------------------------------------------
#define FBQ  128
#define FBKV 128

#define QS_U 0
#define KS_U (128 * 36)                          // 4608
#define VP_U (KS_U + 2 * 128 * 36)               // 13824
#define FLASH_SMEM ((VP_U + 2 * 64 * 68) * 4)    // 90112 B

__global__ __launch_bounds__(256, 2) void flash_kernel(
    const unsigned short* __restrict__ Q, const unsigned short* __restrict__ K,
    const unsigned* __restrict__ VP, unsigned* __restrict__ Obf)
{
    extern __shared__ unsigned fsm[];
    unsigned (*Qs)[36]      = (unsigned(*)[36])     (fsm + QS_U);
    unsigned (*Ks)[128][36] = (unsigned(*)[128][36])(fsm + KS_U);
    unsigned (*Vp)[64][68]  = (unsigned(*)[64][68]) (fsm + VP_U);

    const int tid  = threadIdx.x;
    const int lane = tid & 31;
    const int wid  = tid >> 5;
    const int qr   = lane >> 2;
    const int qc   = lane & 3;
    const int z    = blockIdx.y;
    const int bb   = z >> 4;
    const int hh   = z & 15;
    const long long baseH = (long long)bb * SEQ * HIDDEN + hh * HEADD;   // halves
    const long long vpb0  = (long long)bb * 1024 * HIDDEN + hh * HEADD;  // u32
    const int q0 = blockIdx.x * FBQ;
    const int r0 = wid * 16;

    const int NT = SEQ / FBKV;

    // load helpers (4 chunks/thread for each tile)
    const int kr = (tid + 0) >> 3;   // reused pattern below

    // ---- prologue: G0 = {Q, K0, V0} ----
    #pragma unroll
    for (int it = 0; it < 4; ++it) {
        int c = tid + it * 256;
        int r = c >> 3, ch = c & 7;
        cp16(&Qs[r][ch * 4], Q + baseH + (long long)(q0 + r) * HIDDEN + ch * 8);
    }
    #pragma unroll
    for (int it = 0; it < 4; ++it) {
        int c = tid + it * 256;
        int r = c >> 3, ch = c & 7;
        cp16(&Ks[0][r][ch * 4], K + baseH + (long long)r * HIDDEN + ch * 8);
    }
    #pragma unroll
    for (int it = 0; it < 4; ++it) {
        int c = tid + it * 256;
        int r = c >> 4, ch = c & 15;
        cp16(&Vp[0][r][ch * 4], VP + vpb0 + (long long)r * HIDDEN + ch * 4);
    }
    CP_COMMIT();
    // ---- G1 = {K1, V1} ----
    {
        const long long kb2 = baseH + (long long)FBKV * HIDDEN;
        const long long vb2 = vpb0 + (long long)64 * HIDDEN;
        #pragma unroll
        for (int it = 0; it < 4; ++it) {
            int c = tid + it * 256;
            int r = c >> 3, ch = c & 7;
            cp16(&Ks[1][r][ch * 4], K + kb2 + (long long)r * HIDDEN + ch * 8);
        }
        #pragma unroll
        for (int it = 0; it < 4; ++it) {
            int c = tid + it * 256;
            int r = c >> 4, ch = c & 15;
            cp16(&Vp[1][r][ch * 4], VP + vb2 + (long long)r * HIDDEN + ch * 4);
        }
        CP_COMMIT();
    }

    float accO[8][4];
    #pragma unroll
    for (int ni = 0; ni < 8; ++ni)
        #pragma unroll
        for (int r = 0; r < 4; ++r) accO[ni][r] = 0.0f;
    float m0 = -1e30f, m1 = -1e30f, l0 = 0.0f, l1 = 0.0f;

    for (int t = 0; t < NT; ++t) {
        if (t + 1 < NT) { CP_WAIT1(); } else { CP_WAIT0(); }  // G(t) resident
        __syncthreads();
        const int s = t & 1;

        // ---- S = Q @ K^T ----
        float accS[16][4];
        #pragma unroll
        for (int nt = 0; nt < 16; ++nt)
            #pragma unroll
            for (int r = 0; r < 4; ++r) accS[nt][r] = 0.0f;

        #pragma unroll
        for (int ks = 0; ks < 4; ++ks) {
            const int kb = ks * 8;
            unsigned a0 = Qs[r0 + qr][kb + qc];
            unsigned a1 = Qs[r0 + qr + 8][kb + qc];
            unsigned a2 = Qs[r0 + qr][kb + qc + 4];
            unsigned a3 = Qs[r0 + qr + 8][kb + qc + 4];
            #pragma unroll
            for (int nt = 0; nt < 16; ++nt) {
                unsigned b0 = Ks[s][nt * 8 + qr][kb + qc];
                unsigned b1 = Ks[s][nt * 8 + qr][kb + qc + 4];
                mma16(accS[nt], a0, a1, a2, a3, b0, b1);
            }
        }

        // ---- online softmax ----
        float rm0 = -1e30f, rm1 = -1e30f;
        #pragma unroll
        for (int nt = 0; nt < 16; ++nt) {
            accS[nt][0] *= 0.125f; accS[nt][1] *= 0.125f;
            accS[nt][2] *= 0.125f; accS[nt][3] *= 0.125f;
            rm0 = fmaxf(rm0, fmaxf(accS[nt][0], accS[nt][1]));
            rm1 = fmaxf(rm1, fmaxf(accS[nt][2], accS[nt][3]));
        }
        rm0 = fmaxf(rm0, __shfl_xor_sync(0xFFFFFFFFu, rm0, 1));
        rm0 = fmaxf(rm0, __shfl_xor_sync(0xFFFFFFFFu, rm0, 2));
        rm1 = fmaxf(rm1, __shfl_xor_sync(0xFFFFFFFFu, rm1, 1));
        rm1 = fmaxf(rm1, __shfl_xor_sync(0xFFFFFFFFu, rm1, 2));

        float nm0 = fmaxf(m0, rm0), nm1 = fmaxf(m1, rm1);
        float cr_0 = __expf(m0 - nm0), cr_1 = __expf(m1 - nm1);
        m0 = nm0; m1 = nm1;

        float s0 = 0.0f, s1 = 0.0f;
        #pragma unroll
        for (int nt = 0; nt < 16; ++nt) {
            float p0 = __expf(accS[nt][0] - m0);
            float p1 = __expf(accS[nt][1] - m0);
            float p2 = __expf(accS[nt][2] - m1);
            float p3 = __expf(accS[nt][3] - m1);
            unsigned p01 = pack_bf16(p0, p1);
            unsigned p23 = pack_bf16(p2, p3);
            s0 += __uint_as_float(p01 << 16) + __uint_as_float(p01 & 0xFFFF0000u);
            s1 += __uint_as_float(p23 << 16) + __uint_as_float(p23 & 0xFFFF0000u);
            accS[nt][0] = __uint_as_float(p01);
            accS[nt][1] = __uint_as_float(p23);
        }
        s0 += __shfl_xor_sync(0xFFFFFFFFu, s0, 1);
        s0 += __shfl_xor_sync(0xFFFFFFFFu, s0, 2);
        s1 += __shfl_xor_sync(0xFFFFFFFFu, s1, 1);
        s1 += __shfl_xor_sync(0xFFFFFFFFu, s1, 2);
        l0 = l0 * cr_0 + s0;
        l1 = l1 * cr_1 + s1;

        #pragma unroll
        for (int ni = 0; ni < 8; ++ni) {
            accO[ni][0] *= cr_0; accO[ni][1] *= cr_0;
            accO[ni][2] *= cr_1; accO[ni][3] *= cr_1;
        }

        // ---- O += P @ V ----
        #pragma unroll
        for (int ks = 0; ks < 8; ++ks) {
            unsigned a0 = __float_as_uint(accS[2*ks][0]);
            unsigned a1 = __float_as_uint(accS[2*ks][1]);
            unsigned a2 = __float_as_uint(accS[2*ks+1][0]);
            unsigned a3 = __float_as_uint(accS[2*ks+1][1]);
            #pragma unroll
            for (int ni = 0; ni < 8; ++ni) {
                unsigned b0 = Vp[s][8*ks + qc][ni * 8 + qr];
                unsigned b1 = Vp[s][8*ks + qc + 4][ni * 8 + qr];
                mma16(accO[ni], a0, a1, a2, a3, b0, b1);
            }
        }
        __syncthreads();            // all warps done reading buf s

        // ---- commit G(t+2) into buf s ----
        if (t + 2 < NT) {
            const long long kb2 = baseH + (long long)(t + 2) * FBKV * HIDDEN;
            const long long vb2 = vpb0 + (long long)(t + 2) * 64 * HIDDEN;
            #pragma unroll
            for (int it = 0; it < 4; ++it) {
                int c = tid + it * 256;
                int r = c >> 3, ch = c & 7;
                cp16(&Ks[s][r][ch * 4], K + kb2 + (long long)r * HIDDEN + ch * 8);
            }
            #pragma unroll
            for (int it = 0; it < 4; ++it) {
                int c = tid + it * 256;
                int r = c >> 4, ch = c & 15;
                cp16(&Vp[s][r][ch * 4], VP + vb2 + (long long)r * HIDDEN + ch * 4);
            }
            CP_COMMIT();
        }
    }

    // ---- epilogue: normalize, store ctx (bf16) ----
    float i0 = 1.0f / l0, i1 = 1.0f / l1;
    const long long obase = ((long long)bb * SEQ) * HHALF + hh * (HEADD / 2);
    #pragma unroll
    for (int ni = 0; ni < 8; ++ni) {
        int cu = ni * 4 + qc;
        Obf[obase + (long long)(q0 + r0 + qr) * HHALF + cu] =
            pack_bf16(accO[ni][0] * i0, accO[ni][1] * i0);
        Obf[obase + (long long)(q0 + r0 + qr + 8) * HHALF + cu] =
            pack_bf16(accO[ni][2] * i1, accO[ni][3] * i1);
    }
}

// ---------------------------------------------------------------------------
// Launch
// ---------------------------------------------------------------------------
extern "C" void kernel_launch(void* const* d_in, const int* in_sizes, int n_in,
                              void* d_out, int out_size)
{
    (void)in_sizes; (void)n_in; (void)out_size;
    const float* x    = (const float*)d_in[0];
    const float* Wq   = (const float*)d_in[1];
    const float* bq   = (const float*)d_in[2];
    const float* Wk   = (const float*)d_in[3];
    const float* bk   = (const float*)d_in[4];
    const float* Wv   = (const float*)d_in[5];
    const float* bv   = (const float*)d_in[6];
    const float* Wo   = (const float*)d_in[7];
    const float* bo   = (const float*)d_in[8];
    const float* ln_g = (const float*)d_in[9];
    const float* ln_b = (const float*)d_in[10];
    float* out = (float*)d_out;

    unsigned short *xn, *q, *k, *v, *ctx, *w;
    unsigned *vp;
    cudaGetSymbolAddress((void**)&xn,  g_xn);
    cudaGetSymbolAddress((void**)&q,   g_q);
    cudaGetSymbolAddress((void**)&k,   g_k);
    cudaGetSymbolAddress((void**)&v,   g_v);
    cudaGetSymbolAddress((void**)&ctx, g_ctx);
    cudaGetSymbolAddress((void**)&vp,  g_vp);
    cudaGetSymbolAddress((void**)&w,   g_w);
    unsigned short* wq = w;
    unsigned short* wk = w + (long long)HIDDEN * HIDDEN;
    unsigned short* wv = w + 2LL * HIDDEN * HIDDEN;
    unsigned short* wo = w + 3LL * HIDDEN * HIDDEN;

    cudaFuncSetAttribute(gemm_bf16_db_kernel<false>,
        cudaFuncAttributeMaxDynamicSharedMemorySize, GEMM_SMEM);
    cudaFuncSetAttribute(gemm_bf16_db_kernel<true>,
        cudaFuncAttributeMaxDynamicSharedMemorySize, GEMM_SMEM);
    cudaFuncSetAttribute(flash_kernel,
        cudaFuncAttributeMaxDynamicSharedMemorySize, FLASH_SMEM);

    // 0) weights -> bf16 (one launch)
    dim3 gConv(1024, 4, 1);
    convw_kernel<<<gConv, 256>>>(Wq, Wk, Wv, Wo, (unsigned*)w);

    // 1) LayerNorm (bf16 out)
    ln_kernel<<<ROWS, 256>>>(x, ln_g, ln_b, (unsigned*)xn);

    // 2) fused Q/K/V projections (bf16 out)
    GemmPtrs pq;
    pq.W[0] = wq; pq.W[1] = wk; pq.W[2] = wv;
    pq.bias[0] = bq; pq.bias[1] = bk; pq.bias[2] = bv;
    pq.C[0] = q; pq.C[1] = k; pq.C[2] = v;
    dim3 gQKV(HIDDEN / TBN, ROWS / TBM, 3);
    gemm_bf16_db_kernel<false><<<gQKV, 256, GEMM_SMEM>>>(xn, pq, nullptr);

    // 3) pair V rows
    vpair_kernel<<<2048, 256>>>(v, vp);

    // 4) flash attention -> ctx (bf16)
    dim3 gFlash(SEQ / FBQ, BATCH * HEADS, 1);
    flash_kernel<<<gFlash, 256, FLASH_SMEM>>>(q, k, vp, (unsigned*)ctx);

    // 5) out = x + ctx @ Wo^T + bo (fp32)
    GemmPtrs po;
    po.W[0] = wo; po.W[1] = wo; po.W[2] = wo;
    po.bias[0] = bo; po.bias[1] = bo; po.bias[2] = bo;
    po.C[0] = out; po.C[1] = out; po.C[2] = out;
    dim3 gOut(HIDDEN / TBN, ROWS / TBM, 1);
    gemm_bf16_db_kernel<true><<<gOut, 256, GEMM_SMEM>>>(ctx, po, x);
}